// round 16
// baseline (speedup 1.0000x reference)
#include <cuda_runtime.h>
#include <cuda_bf16.h>
#include <math.h>
#include <stdint.h>

#define NN 50000
#define EE 800000
#define BB 512
#define DD 128
#define KK 256
#define TM 128
#define GEMM_BLOCKS ((NN + TM - 1) / TM)   // 391

// ---------------- scratch (static device globals; no allocation) ----------------
__device__ float g_h1[NN * DD];               // layer-3 output (for pooling)
// interleaved frag-packed bf16 operand storage: per row, 64 uint4.
// element j = kg*4 + q  (kg 0..15, q 0..3) holds {hi(p), hi(p+4), lo(p), lo(p+4)}
// with pair p = kg*8 + q  (pair p covers columns 2p, 2p+1).
// elements 0..31  (kg 0..7)  = aggregation result (A cols 0..127)
// elements 32..63 (kg 8..15) = h/x split        (A cols 128..255)
__device__ uint4 g_A[NN * 64];
// W^T packed identically: [n*64 + kg*4 + q] = {hi, hi(+4), lo, lo(+4)}
__device__ uint4 g_W[3][DD * 64];
__device__ float g_pool[BB * DD];
__device__ float g_invdeg[NN];
__device__ int   g_deg[NN];
__device__ int   g_rowptr[NN + 1];
__device__ int   g_col[EE];
__device__ int   g_root[BB];

// bf16x2 unpack via bit ops (bf16 -> fp32 is a 16-bit shift)
__device__ __forceinline__ float bf_lo(uint32_t u) { return __uint_as_float(u << 16); }
__device__ __forceinline__ float bf_hi(uint32_t u) { return __uint_as_float(u & 0xFFFF0000u); }

// ---------------- fp32 -> bf16 hi/lo split ----------------
__device__ __forceinline__ void split2(float a, float b, uint32_t& hi, uint32_t& lo) {
    __nv_bfloat16 ha = __float2bfloat16(a);
    __nv_bfloat16 hb = __float2bfloat16(b);
    __nv_bfloat16 la = __float2bfloat16(a - __bfloat162float(ha));
    __nv_bfloat16 lb = __float2bfloat16(b - __bfloat162float(hb));
    hi = ((uint32_t)__bfloat16_as_ushort(hb) << 16) | __bfloat16_as_ushort(ha);
    lo = ((uint32_t)__bfloat16_as_ushort(lb) << 16) | __bfloat16_as_ushort(la);
}

// ---------------- init: zero deg + pool ----------------
__global__ void k_init() {
    int i = blockIdx.x * blockDim.x + threadIdx.x;
    if (i < NN) g_deg[i] = 0;
    if (i < BB * DD) ((int*)g_pool)[i] = 0;          // 0 bits == +0.0f
}

__global__ void k_count(const int* __restrict__ dst) {
    int e = blockIdx.x * blockDim.x + threadIdx.x;
    if (e < EE) atomicAdd(&g_deg[dst[e]], 1);
}

// exclusive scan + invdeg + cursor reset + roots, single block
__global__ void k_scan_fused(const int* __restrict__ batch) {
    __shared__ int wsum[32];
    __shared__ int carry;
    int tid = threadIdx.x;
    int warp = tid >> 5, lane = tid & 31;
    if (tid == 0) carry = 0;
    __syncthreads();
    for (int base = 0; base < NN; base += 1024) {
        int i = base + tid;
        int v = (i < NN) ? g_deg[i] : 0;
        int s = v;
#pragma unroll
        for (int off = 1; off < 32; off <<= 1) {
            int t = __shfl_up_sync(0xFFFFFFFFu, s, off);
            if (lane >= off) s += t;
        }
        if (lane == 31) wsum[warp] = s;
        __syncthreads();
        if (warp == 0) {
            int w = wsum[lane];
#pragma unroll
            for (int off = 1; off < 32; off <<= 1) {
                int t = __shfl_up_sync(0xFFFFFFFFu, w, off);
                if (lane >= off) w += t;
            }
            wsum[lane] = w;
        }
        __syncthreads();
        int off = carry + (warp ? wsum[warp - 1] : 0);
        if (i < NN) {
            g_rowptr[i] = off + s - v;
            g_invdeg[i] = 1.0f / (float)(v > 1 ? v : 1);
            g_deg[i] = 0;                          // reuse as fill cursor
            int b = batch[i];
            if (i == 0 || batch[i - 1] != b) g_root[b] = i;
        }
        __syncthreads();
        if (tid == 0) carry += wsum[31];
        __syncthreads();
    }
    if (tid == 0) g_rowptr[NN] = carry;
}

__global__ void k_fill(const int* __restrict__ src, const int* __restrict__ dst) {
    int e = blockIdx.x * blockDim.x + threadIdx.x;
    if (e < EE) {
        int d = dst[e];
        int pos = g_rowptr[d] + atomicAdd(&g_deg[d], 1);
        g_col[pos] = src[e];
    }
}

// W^T hi/lo split for all 3 layers, uint4-frag-packed
__global__ void k_prep_w(const float* __restrict__ Wl1, const float* __restrict__ Wr1,
                         const float* __restrict__ Wl2, const float* __restrict__ Wr2,
                         const float* __restrict__ Wl3, const float* __restrict__ Wr3) {
    int gidx = blockIdx.x * blockDim.x + threadIdx.x;
    const int PER = DD * 64;                    // 8192 uint4 per layer
    int layer = gidx / PER;
    if (layer >= 3) return;
    int idx = gidx - layer * PER;
    const float* Wl = layer == 0 ? Wl1 : (layer == 1 ? Wl2 : Wl3);
    const float* Wr = layer == 0 ? Wr1 : (layer == 1 ? Wr2 : Wr3);
    int n = idx >> 6;            // 0..127
    int g = idx & 63;            // kg*4 + q
    int kg = g >> 2, q = g & 3;
    int kc0 = kg * 16 + q * 2;
    float w[4];
#pragma unroll
    for (int t = 0; t < 4; ++t) {
        int col = kc0 + (t >> 1) * 8 + (t & 1);
        w[t] = (col < 128) ? Wl[col * 128 + n] : Wr[(col - 128) * 128 + n];
    }
    uint4 v;
    split2(w[0], w[1], v.x, v.z);
    split2(w[2], w[3], v.y, v.w);
    g_W[layer][n * 64 + g] = v;
}

// ---------------- mean aggregation: warp per node ----------------
// lane -> (kg = lane>>2, q = lane&3); owns cols c0,c0+1,c0+8,c0+9 with c0 = kg*16+q*2
__global__ void __launch_bounds__(256) k_agg(const float* __restrict__ x,
                                             int use_split, int do_x) {
    int warp = (blockIdx.x * blockDim.x + threadIdx.x) >> 5;
    int lane = threadIdx.x & 31;
    if (warp >= NN) return;
    int kg = lane >> 2, q = lane & 3;
    int c0 = kg * 16 + q * 2;
    int el = kg * 4 + q;                       // uint4 element index
    int s = g_rowptr[warp];
    int e = g_rowptr[warp + 1];
    float a0 = 0.f, a1 = 0.f, a2 = 0.f, a3 = 0.f;
    float b0 = 0.f, b1 = 0.f, b2 = 0.f, b3 = 0.f;
    float c0f = 0.f, c1f = 0.f, c2f = 0.f, c3f = 0.f;
    float d0 = 0.f, d1 = 0.f, d2 = 0.f, d3 = 0.f;
    int i = s;
    if (use_split) {
        int off = 32 + el;
        for (; i + 4 <= e; i += 4) {
            int n0 = g_col[i], n1 = g_col[i + 1], n2 = g_col[i + 2], n3 = g_col[i + 3];
            uint4 u0 = g_A[(size_t)n0 * 64 + off];
            uint4 u1 = g_A[(size_t)n1 * 64 + off];
            uint4 u2 = g_A[(size_t)n2 * 64 + off];
            uint4 u3 = g_A[(size_t)n3 * 64 + off];
            a0 += bf_lo(u0.x) + bf_lo(u0.z); a1 += bf_hi(u0.x) + bf_hi(u0.z);
            a2 += bf_lo(u0.y) + bf_lo(u0.w); a3 += bf_hi(u0.y) + bf_hi(u0.w);
            b0 += bf_lo(u1.x) + bf_lo(u1.z); b1 += bf_hi(u1.x) + bf_hi(u1.z);
            b2 += bf_lo(u1.y) + bf_lo(u1.w); b3 += bf_hi(u1.y) + bf_hi(u1.w);
            c0f += bf_lo(u2.x) + bf_lo(u2.z); c1f += bf_hi(u2.x) + bf_hi(u2.z);
            c2f += bf_lo(u2.y) + bf_lo(u2.w); c3f += bf_hi(u2.y) + bf_hi(u2.w);
            d0 += bf_lo(u3.x) + bf_lo(u3.z); d1 += bf_hi(u3.x) + bf_hi(u3.z);
            d2 += bf_lo(u3.y) + bf_lo(u3.w); d3 += bf_hi(u3.y) + bf_hi(u3.w);
        }
        for (; i < e; ++i) {
            int n0 = g_col[i];
            uint4 u0 = g_A[(size_t)n0 * 64 + off];
            a0 += bf_lo(u0.x) + bf_lo(u0.z); a1 += bf_hi(u0.x) + bf_hi(u0.z);
            a2 += bf_lo(u0.y) + bf_lo(u0.w); a3 += bf_hi(u0.y) + bf_hi(u0.w);
        }
    } else {
        for (; i + 4 <= e; i += 4) {
            int n0 = g_col[i], n1 = g_col[i + 1], n2 = g_col[i + 2], n3 = g_col[i + 3];
            float2 u0 = *(const float2*)(x + (size_t)n0 * DD + c0);
            float2 v0 = *(const float2*)(x + (size_t)n0 * DD + c0 + 8);
            float2 u1 = *(const float2*)(x + (size_t)n1 * DD + c0);
            float2 v1 = *(const float2*)(x + (size_t)n1 * DD + c0 + 8);
            float2 u2 = *(const float2*)(x + (size_t)n2 * DD + c0);
            float2 v2 = *(const float2*)(x + (size_t)n2 * DD + c0 + 8);
            float2 u3 = *(const float2*)(x + (size_t)n3 * DD + c0);
            float2 v3 = *(const float2*)(x + (size_t)n3 * DD + c0 + 8);
            a0 += u0.x; a1 += u0.y; a2 += v0.x; a3 += v0.y;
            b0 += u1.x; b1 += u1.y; b2 += v1.x; b3 += v1.y;
            c0f += u2.x; c1f += u2.y; c2f += v2.x; c3f += v2.y;
            d0 += u3.x; d1 += u3.y; d2 += v3.x; d3 += v3.y;
        }
        for (; i < e; ++i) {
            int n0 = g_col[i];
            float2 u0 = *(const float2*)(x + (size_t)n0 * DD + c0);
            float2 v0 = *(const float2*)(x + (size_t)n0 * DD + c0 + 8);
            a0 += u0.x; a1 += u0.y; a2 += v0.x; a3 += v0.y;
        }
    }
    float iv = g_invdeg[warp];
    float m0 = (a0 + b0 + c0f + d0) * iv;
    float m1 = (a1 + b1 + c1f + d1) * iv;
    float m2 = (a2 + b2 + c2f + d2) * iv;
    float m3 = (a3 + b3 + c3f + d3) * iv;
    uint4 o;
    split2(m0, m1, o.x, o.z);
    split2(m2, m3, o.y, o.w);
    g_A[(size_t)warp * 64 + el] = o;
    if (do_x) {   // layer 1: also split own x row into h-region
        float2 u = *(const float2*)(x + (size_t)warp * DD + c0);
        float2 v = *(const float2*)(x + (size_t)warp * DD + c0 + 8);
        uint4 o2;
        split2(u.x, u.y, o2.x, o2.z);
        split2(v.x, v.y, o2.y, o2.w);
        g_A[(size_t)warp * 64 + 32 + el] = o2;
    }
}

// ---------------- HMMA helper ----------------
__device__ __forceinline__ void mma16816(float* c, const uint32_t* a, const uint32_t* b) {
    asm volatile(
        "mma.sync.aligned.m16n8k16.row.col.f32.bf16.bf16.f32 "
        "{%0,%1,%2,%3}, {%4,%5,%6,%7}, {%8,%9}, {%0,%1,%2,%3};"
        : "+f"(c[0]), "+f"(c[1]), "+f"(c[2]), "+f"(c[3])
        : "r"(a[0]), "r"(a[1]), "r"(a[2]), "r"(a[3]), "r"(b[0]), "r"(b[1]));
}

// ---------------- HMMA GEMM with smem-staged tiles ----------------
// write_mode: 1 = write bf16 split into h-region (layers 1,2); 0 = write fp32 g_h1 (layer 3)
#define SSTRIDE 5   // uint4 per smem row (4 data + 1 pad)
__global__ void __launch_bounds__(256) k_gemm_hmma(const float* __restrict__ bias,
                                                   int layer, int write_mode) {
    __shared__ uint4 As[TM * SSTRIDE];
    __shared__ uint4 Bs[DD * SSTRIDE];

    int tid = threadIdx.x;
    int wid = tid >> 5;
    int lane = tid & 31;
    int wm = wid & 3;
    int wn = wid >> 2;
    int block_m = blockIdx.x * TM;

    const uint4* W = g_W[layer];
    int grp = lane >> 2;
    int quad = lane & 3;

    // loader indices: 2 A elements + 2 B elements per thread per kg
    int li0 = tid;              // 0..255
    int li1 = tid + 256;        // 256..511
    int ar0 = li0 >> 2, aq0 = li0 & 3;
    int ar1 = li1 >> 2, aq1 = li1 & 3;
    int am0 = block_m + ar0 < NN ? block_m + ar0 : NN - 1;
    int am1 = block_m + ar1 < NN ? block_m + ar1 : NN - 1;

    float acc[2][8][4];
#pragma unroll
    for (int mi = 0; mi < 2; ++mi)
#pragma unroll
        for (int ni = 0; ni < 8; ++ni)
#pragma unroll
            for (int r = 0; r < 4; ++r) acc[mi][ni][r] = 0.f;

    // prefetch kg=0
    uint4 rA0 = g_A[(size_t)am0 * 64 + aq0];
    uint4 rA1 = g_A[(size_t)am1 * 64 + aq1];
    uint4 rB0 = W[ar0 * 64 + aq0];
    uint4 rB1 = W[ar1 * 64 + aq1];

#pragma unroll 1
    for (int kg = 0; kg < 16; ++kg) {
        As[ar0 * SSTRIDE + aq0] = rA0;
        As[ar1 * SSTRIDE + aq1] = rA1;
        Bs[ar0 * SSTRIDE + aq0] = rB0;
        Bs[ar1 * SSTRIDE + aq1] = rB1;
        __syncthreads();
        if (kg < 15) {
            int el = (kg + 1) * 4;
            rA0 = g_A[(size_t)am0 * 64 + el + aq0];
            rA1 = g_A[(size_t)am1 * 64 + el + aq1];
            rB0 = W[ar0 * 64 + el + aq0];
            rB1 = W[ar1 * 64 + el + aq1];
        }
        uint32_t ah[2][4], al[2][4];
#pragma unroll
        for (int mi = 0; mi < 2; ++mi) {
            int rr = wm * 32 + mi * 16 + grp;
            uint4 u0 = As[rr * SSTRIDE + quad];
            uint4 u1 = As[(rr + 8) * SSTRIDE + quad];
            ah[mi][0] = u0.x; ah[mi][1] = u1.x; ah[mi][2] = u0.y; ah[mi][3] = u1.y;
            al[mi][0] = u0.z; al[mi][1] = u1.z; al[mi][2] = u0.w; al[mi][3] = u1.w;
        }
        uint32_t bh[8][2], blo[8][2];
#pragma unroll
        for (int ni = 0; ni < 8; ++ni) {
            uint4 v = Bs[(wn * 64 + ni * 8 + grp) * SSTRIDE + quad];
            bh[ni][0] = v.x; bh[ni][1] = v.y;
            blo[ni][0] = v.z; blo[ni][1] = v.w;
        }
#pragma unroll
        for (int mi = 0; mi < 2; ++mi)
#pragma unroll
            for (int ni = 0; ni < 8; ++ni) {
                mma16816(acc[mi][ni], ah[mi], bh[ni]);
                mma16816(acc[mi][ni], ah[mi], blo[ni]);
                mma16816(acc[mi][ni], al[mi], bh[ni]);
            }
        __syncthreads();
    }

    // epilogue
#pragma unroll
    for (int mi = 0; mi < 2; ++mi) {
        int r0 = block_m + wm * 32 + mi * 16 + grp;
#pragma unroll
        for (int j = 0; j < 4; ++j) {
            int ni0 = 2 * j, ni1 = 2 * j + 1;
            int col0 = wn * 64 + ni0 * 8 + quad * 2;   // pair pa
            int col1 = col0 + 8;                        // pair pa+4
            float b00 = bias[col0], b01 = bias[col0 + 1];
            float b10 = bias[col1], b11 = bias[col1 + 1];
            int el = 32 + (wn * 4 + j) * 4 + quad;      // h-region uint4 element
#pragma unroll
            for (int h = 0; h < 2; ++h) {
                int r = r0 + h * 8;
                if (r >= NN) continue;
                float vx0 = fmaxf(acc[mi][ni0][h * 2 + 0] + b00, 0.f);
                float vy0 = fmaxf(acc[mi][ni0][h * 2 + 1] + b01, 0.f);
                float vx1 = fmaxf(acc[mi][ni1][h * 2 + 0] + b10, 0.f);
                float vy1 = fmaxf(acc[mi][ni1][h * 2 + 1] + b11, 0.f);
                if (write_mode) {
                    uint4 o;
                    split2(vx0, vy0, o.x, o.z);
                    split2(vx1, vy1, o.y, o.w);
                    g_A[(size_t)r * 64 + el] = o;
                } else {
                    *(float2*)(g_h1 + (size_t)r * DD + col0) = make_float2(vx0, vy0);
                    *(float2*)(g_h1 + (size_t)r * DD + col1) = make_float2(vx1, vy1);
                }
            }
        }
    }
}

// ---------------- pooling: 128 threads per block, 64 nodes, flush on graph change ----------------
#define POOL_NODES 64
__global__ void __launch_bounds__(128) k_pool2(const int* __restrict__ batch) {
    int n0 = blockIdx.x * POOL_NODES;
    int col = threadIdx.x;
    if (n0 >= NN) return;
    int nend = n0 + POOL_NODES; if (nend > NN) nend = NN;
    int cur = batch[n0];
    float m = 0.f;
    for (int n = n0; n < nend; ++n) {
        int b = batch[n];
        if (b != cur) {
            atomicMax((int*)g_pool + (size_t)cur * DD + col, __float_as_int(m));
            m = 0.f;
            cur = b;
        }
        m = fmaxf(m, g_h1[(size_t)n * DD + col]);
    }
    atomicMax((int*)g_pool + (size_t)cur * DD + col, __float_as_int(m));
}

// ---------------- per-graph MLP head ----------------
__global__ void __launch_bounds__(256) k_head(const float* __restrict__ x,
                                              const float* __restrict__ Wf1, const float* __restrict__ bf1,
                                              const float* __restrict__ Wf2, const float* __restrict__ bf2,
                                              const float* __restrict__ Wsm, const float* __restrict__ bsm,
                                              const float* __restrict__ Wnews, const float* __restrict__ bnews,
                                              const float* __restrict__ Wcat, const float* __restrict__ bcat,
                                              float* __restrict__ out) {
    int b = blockIdx.x;
    int t = threadIdx.x;
    __shared__ float p[128], xr[128], t1[256], t2[128], sres[4];
    if (t < 128) {
        p[t] = g_pool[(size_t)b * DD + t];
        xr[t] = x[(size_t)g_root[b] * DD + t];
    }
    __syncthreads();
    {
        float acc = bf1[t];
#pragma unroll 4
        for (int k = 0; k < 128; k++) acc += p[k] * Wf1[k * 256 + t];
        t1[t] = fmaxf(acc, 0.f);
    }
    __syncthreads();
    if (t < 128) {
        float acc = bf2[t];
#pragma unroll 4
        for (int k = 0; k < 256; k++) acc += t1[k] * Wf2[k * 128 + t];
        t2[t] = fmaxf(acc, 0.f);
    }
    __syncthreads();
    if (t < 2) {
        float acc = bsm[t];
        for (int k = 0; k < 128; k++) acc += t2[k] * Wsm[k * 2 + t];
        sres[t] = fmaxf(acc, 0.f);
        float a2 = bnews[t];
        for (int k = 0; k < 128; k++) a2 += xr[k] * Wnews[k * 2 + t];
        sres[2 + t] = fmaxf(a2, 0.f);
    }
    __syncthreads();
    if (t == 0) {
        float o = bcat[0];
        for (int k = 0; k < 4; k++) o += sres[k] * Wcat[k];
        out[b] = 1.f / (1.f + expf(-o));
    }
}

// ---------------- launch ----------------
extern "C" void kernel_launch(void* const* d_in, const int* in_sizes, int n_in,
                              void* d_out, int out_size) {
    const float* x     = (const float*)d_in[0];
    const int*   ei    = (const int*)d_in[1];
    const int*   src   = ei;
    const int*   dst   = ei + EE;
    const int*   batch = (const int*)d_in[2];
    const float* Wl1 = (const float*)d_in[3];
    const float* Wr1 = (const float*)d_in[4];
    const float* bl1 = (const float*)d_in[5];
    const float* Wl2 = (const float*)d_in[6];
    const float* Wr2 = (const float*)d_in[7];
    const float* bl2 = (const float*)d_in[8];
    const float* Wl3 = (const float*)d_in[9];
    const float* Wr3 = (const float*)d_in[10];
    const float* bl3 = (const float*)d_in[11];
    const float* Wf1 = (const float*)d_in[12];
    const float* bf1 = (const float*)d_in[13];
    const float* Wf2 = (const float*)d_in[14];
    const float* bf2 = (const float*)d_in[15];
    const float* Wsm = (const float*)d_in[16];
    const float* bsm = (const float*)d_in[17];
    const float* Wnews = (const float*)d_in[18];
    const float* bnews = (const float*)d_in[19];
    const float* Wcat = (const float*)d_in[20];
    const float* bcat = (const float*)d_in[21];
    float* out = (float*)d_out;

    const int TB = 256;
    int gE = (EE + TB - 1) / TB;
    int gWarpN = (NN * 32 + TB - 1) / TB;
    int gPrep = (3 * DD * 64 + TB - 1) / TB;

    k_init<<<256, TB>>>();                       // 1
    k_count<<<gE, TB>>>(dst);                    // 2
    k_scan_fused<<<1, 1024>>>(batch);            // 3
    k_fill<<<gE, TB>>>(src, dst);                // 4  <- profiled launch
    k_prep_w<<<gPrep, TB>>>(Wl1, Wr1, Wl2, Wr2, Wl3, Wr3);   // 5

    // layer 1: agg(x) + x-split, GEMM -> split only
    k_agg<<<gWarpN, TB>>>(x, 0, 1);              // 6
    k_gemm_hmma<<<GEMM_BLOCKS, 256>>>(bl1, 0, 1);   // 7
    // layer 2: agg(split), GEMM -> split only
    k_agg<<<gWarpN, TB>>>(nullptr, 1, 0);        // 8
    k_gemm_hmma<<<GEMM_BLOCKS, 256>>>(bl2, 1, 1);   // 9
    // layer 3: agg(split), GEMM -> fp32 h1
    k_agg<<<gWarpN, TB>>>(nullptr, 1, 0);        // 10
    k_gemm_hmma<<<GEMM_BLOCKS, 256>>>(bl3, 2, 0);   // 11

    k_pool2<<<(NN + POOL_NODES - 1) / POOL_NODES, 128>>>(batch);  // 12
    k_head<<<BB, TB>>>(x, Wf1, bf1, Wf2, bf2, Wsm, bsm, Wnews, bnews, Wcat, bcat, out);  // 13
}